// round 16
// baseline (speedup 1.0000x reference)
#include <cuda_runtime.h>
#include <cuda_fp16.h>
#include <cstdint>
#include <cstddef>

// ---------------- problem dims (fixed) ----------------
#define NTOK 8192            // 4*2048 tokens
#define HDIM 1024
#define DDIM 4096
// K reduced 9216 -> 8192 via B-spline partition of unity (W_7 folds into a bias).
#define KDIM 8192

// ---------------- GEMM tiling (R15 champion config) ----------------
#define TILE_M 128
#define TILE_N 128
#define KCHUNK 64            // fp16 elems per k-iter = 128 bytes per row
#define STAGES 3
#define NIT (KDIM / KCHUNK)  // 128
#define GTHREADS 256         // 8 warps: 2 (M) x 4 (N), warp tile 64x32
#define MT (NTOK / TILE_M)   // 64
#define NT (DDIM / TILE_N)   // 32
#define NTILES (MT * NT)     // 2048
#define GRID 304             // 2 CTAs/SM * 152 SMs; persistent + work stealing

#define A_STAGE_BYTES (TILE_M * 128)   // 16384
#define B_STAGE_BYTES (TILE_N * 128)   // 16384
#define STAGE_BYTES (A_STAGE_BYTES + B_STAGE_BYTES)
#define DYN_SMEM (STAGES * STAGE_BYTES + 1024)   // ~97 KB -> 2 CTAs/SM

// ---------------- scratch (allocation-free: __device__ globals) ----------------
__device__ __half g_act[(size_t)NTOK * KDIM];   // 134 MB fp16 features
__device__ __half g_w[(size_t)DDIM * KDIM];     // 67 MB fp16 fused weights
__device__ float g_biasp[DDIM][4];              // 4 deterministic bias partials per output
__device__ int g_tile_ctr;                      // work-stealing ticket counter

// ---------------- helpers ----------------
__device__ __forceinline__ void cp_async16(uint32_t dst, const void* src) {
    asm volatile("cp.async.cg.shared.global [%0], [%1], 16;"
                 :: "r"(dst), "l"(src) : "memory");
}

__device__ __forceinline__ float gelu_exact(float v) {
    return 0.5f * v * (1.0f + erff(v * 0.70710678118654752f));
}

__device__ __forceinline__ void ldsm_x4(uint32_t* r, uint32_t addr) {
    asm volatile("ldmatrix.sync.aligned.m8n8.x4.shared.b16 {%0,%1,%2,%3}, [%4];"
                 : "=r"(r[0]), "=r"(r[1]), "=r"(r[2]), "=r"(r[3]) : "r"(addr));
}

__device__ __forceinline__ void mma_m16n8k16(float* c, const uint32_t* a, const uint32_t* b) {
    asm volatile(
        "mma.sync.aligned.m16n8k16.row.col.f32.f16.f16.f32 "
        "{%0,%1,%2,%3}, {%4,%5,%6,%7}, {%8,%9}, {%0,%1,%2,%3};"
        : "+f"(c[0]), "+f"(c[1]), "+f"(c[2]), "+f"(c[3])
        : "r"(a[0]), "r"(a[1]), "r"(a[2]), "r"(a[3]), "r"(b[0]), "r"(b[1]));
}

// streaming (evict-first) 8-byte store
__device__ __forceinline__ void stg_cs_v2(float* ptr, float x, float y) {
    asm volatile("st.global.cs.v2.f32 [%0], {%1, %2};"
                 :: "l"(ptr), "f"(x), "f"(y) : "memory");
}

// pack 8 floats -> uint4 of fp16
__device__ __forceinline__ uint4 pack8_h(const float* v) {
    union { __half2 h2[4]; uint4 u; } u;
    u.h2[0] = __floats2half2_rn(v[0], v[1]);
    u.h2[1] = __floats2half2_rn(v[2], v[3]);
    u.h2[2] = __floats2half2_rn(v[4], v[5]);
    u.h2[3] = __floats2half2_rn(v[6], v[7]);
    return u.u;
}

// closed-form uniform cubic B-spline features for one x: v[0]=silu, v[1..7]=B_0..B_6
__device__ __forceinline__ void features8(float xv, float* v) {
    float sig = 1.0f / (1.0f + __expf(-xv));
    float silu = xv * sig;

    float t25 = (xv + 1.0f) * 2.5f;
    int i = (int)t25;
    i = i < 0 ? 0 : (i > 4 ? 4 : i);
    float u = t25 - (float)i;
    float u2 = u * u;
    float u3 = u2 * u;
    float om = 1.0f - u;
    const float c6 = 1.0f / 6.0f;
    float b0 = om * om * om * c6;
    float b1 = (3.0f * u3 - 6.0f * u2 + 4.0f) * c6;
    float b2 = (-3.0f * u3 + 3.0f * u2 + 3.0f * u + 1.0f) * c6;
    float b3 = u3 * c6;

    v[0]=silu; v[1]=0.f; v[2]=0.f; v[3]=0.f; v[4]=0.f; v[5]=0.f; v[6]=0.f; v[7]=0.f;
    switch (i) {   // bases occupy slots 1+i .. 1+i+3 (B_7 folded into bias)
        case 0: v[1]=b0; v[2]=b1; v[3]=b2; v[4]=b3; break;
        case 1: v[2]=b0; v[3]=b1; v[4]=b2; v[5]=b3; break;
        case 2: v[3]=b0; v[4]=b1; v[5]=b2; v[6]=b3; break;
        case 3: v[4]=b0; v[5]=b1; v[6]=b2; v[7]=b3; break;
        default: v[5]=b0; v[6]=b1; v[7]=b2; break;
    }
}

// tile id -> (mt, nt), grouped 16x16 for L2 residency
__device__ __forceinline__ void map_tile(int t, int& mt, int& nt) {
    int g = t >> 8;
    int r = t & 255;
    mt = ((g & 3) << 4) | (r & 15);
    nt = ((g >> 2) << 4) | (r >> 4);
}

// ---------------- merged prep kernel ----------------
// act part: 4 elements per thread (float4 read, 4x ILP, 64B coalesced stores)
#define ACT_BLOCKS ((NTOK * HDIM) / (256 * 4))   // 8192
#define W_BLOCKS ((DDIM * HDIM) / 256)           // 16384

__global__ void __launch_bounds__(256) prep_kernel(const float* __restrict__ x,
                                                   const float* __restrict__ bw,
                                                   const float* __restrict__ sw,
                                                   const float* __restrict__ ss) {
    __shared__ float red[8];
    if (blockIdx.x == 0 && threadIdx.x == 0)
        g_tile_ctr = GRID;   // reset stealing counter every launch (prep precedes gemm)

    if (blockIdx.x < ACT_BLOCKS) {
        int idx4 = blockIdx.x * 256 + threadIdx.x;     // group of 4 elements
        float4 xv4 = reinterpret_cast<const float4*>(x)[idx4];
        float xs[4] = {xv4.x, xv4.y, xv4.z, xv4.w};

        int base_idx = idx4 << 2;                      // element index (h mult of 4)
        int n = base_idx >> 10;
        int h0 = base_idx & 1023;
        __half* dst = &g_act[(size_t)n * KDIM + 8 * (size_t)h0];

        uint4 packed[4];
#pragma unroll
        for (int j = 0; j < 4; j++) {
            float v[8];
            features8(xs[j], v);
            packed[j] = pack8_h(v);
        }
#pragma unroll
        for (int j = 0; j < 4; j++)
            reinterpret_cast<uint4*>(dst)[j] = packed[j];
    } else {
        int bidx = blockIdx.x - ACT_BLOCKS;
        int idx = bidx * 256 + threadIdx.x;
        float base = bw[idx];
        float scal = ss[idx];
        int d = idx >> 10;
        int h = idx & 1023;

        const float4* swp = reinterpret_cast<const float4*>(sw + (size_t)idx * 8);
        float4 s0 = swp[0], s1 = swp[1];
        float w7 = s1.w * scal;

        float w[8];
        w[0] = base;
        w[1] = s0.x * scal - w7; w[2] = s0.y * scal - w7;
        w[3] = s0.z * scal - w7; w[4] = s0.w * scal - w7;
        w[5] = s1.x * scal - w7; w[6] = s1.y * scal - w7;
        w[7] = s1.z * scal - w7;

        *reinterpret_cast<uint4*>(&g_w[(size_t)d * KDIM + 8 * (size_t)h]) = pack8_h(w);

        // deterministic bias partial: sum of w7 over this block's 256 h-values
        float s = w7;
#pragma unroll
        for (int m = 16; m > 0; m >>= 1)
            s += __shfl_xor_sync(0xFFFFFFFFu, s, m);
        if ((threadIdx.x & 31) == 0) red[threadIdx.x >> 5] = s;
        __syncthreads();
        if (threadIdx.x == 0) {
            float t = ((red[0] + red[1]) + (red[2] + red[3]))
                    + ((red[4] + red[5]) + (red[6] + red[7]));
            g_biasp[d][bidx & 3] = t;
        }
    }
}

// ---------------- GEMM: issue cp.async for k-iter `it` into stage `s` ----------------
__device__ __forceinline__ void issue_loads(uint32_t smem_base,
                                            const char* a_gbase, const char* b_gbase,
                                            int it, int s, int tid) {
    uint32_t a_s = smem_base + (uint32_t)s * STAGE_BYTES;
    uint32_t b_s = a_s + A_STAGE_BYTES;
    const char* a_g = a_gbase + (size_t)it * 128;   // 64 halfs = 128 B per k-iter
    const char* b_g = b_gbase + (size_t)it * 128;

#pragma unroll
    for (int i = 0; i < 4; i++) {
        int c = tid + i * GTHREADS;
        int row = c >> 3, c8 = c & 7;
        uint32_t off = ((uint32_t)row << 7) | ((uint32_t)c8 << 4);
        uint32_t swz = off ^ ((off >> 3) & 0x70u);
        cp_async16(a_s + swz, a_g + (size_t)row * (KDIM * 2) + ((size_t)c8 << 4));
    }
#pragma unroll
    for (int i = 0; i < 4; i++) {
        int c = tid + i * GTHREADS;
        int row = c >> 3, c8 = c & 7;
        uint32_t off = ((uint32_t)row << 7) | ((uint32_t)c8 << 4);
        uint32_t swz = off ^ ((off >> 3) & 0x70u);
        cp_async16(b_s + swz, b_g + (size_t)row * (KDIM * 2) + ((size_t)c8 << 4));
    }
}

// ---------------- persistent GEMM kernel (2 CTAs/SM, work-stealing tiles) ----------------
__global__ void __launch_bounds__(GTHREADS, 2) gemm_kernel(float* __restrict__ out) {
    extern __shared__ char dsmem[];
    __shared__ int s_next;

    const int tid = threadIdx.x;
    const int wid = tid >> 5;
    const int lane = tid & 31;
    const int lane4 = lane >> 2;
    const int lanem = lane & 3;
    const int warp_m = wid & 1;
    const int warp_n = wid >> 1;

    uint32_t smem_raw = (uint32_t)__cvta_generic_to_shared(dsmem);
    uint32_t smem_base = (smem_raw + 1023u) & ~1023u;

    const int xk = lane & 7;
    const int a_row_l = warp_m * 64 + (lane & 15);
    const int a_hi = lane >> 4;
    const int quad = lane >> 3;
    const int b_row_l = warp_n * 32 + ((quad >> 1) << 3) + (lane & 7);
    const int b_lo = quad & 1;

    int tile = blockIdx.x;
    while (tile < NTILES) {
        int mt, nt;
        map_tile(tile, mt, nt);

        const char* a_gbase = (const char*)(g_act + (size_t)mt * TILE_M * KDIM);
        const char* b_gbase = (const char*)(g_w + (size_t)nt * TILE_N * KDIM);

        float acc[4][4][4];
#pragma unroll
        for (int mi = 0; mi < 4; mi++)
#pragma unroll
            for (int ni = 0; ni < 4; ni++)
#pragma unroll
                for (int j = 0; j < 4; j++) acc[mi][ni][j] = 0.0f;

#pragma unroll
        for (int it = 0; it < STAGES - 1; it++) {
            issue_loads(smem_base, a_gbase, b_gbase, it, it, tid);
            asm volatile("cp.async.commit_group;" ::: "memory");
        }

        int cs = 0;
        int ls = STAGES - 1;
        for (int it = 0; it < NIT; it++) {
            asm volatile("cp.async.wait_group 1;" ::: "memory");
            __syncthreads();

            const int nx = it + STAGES - 1;
            if (nx < NIT) issue_loads(smem_base, a_gbase, b_gbase, nx, ls, tid);
            if (++ls == STAGES) ls = 0;
            asm volatile("cp.async.commit_group;" ::: "memory");

            const uint32_t a_base = smem_base + (uint32_t)cs * STAGE_BYTES;
            const uint32_t b_base = a_base + A_STAGE_BYTES;
            if (++cs == STAGES) cs = 0;

#pragma unroll
            for (int ks = 0; ks < 4; ks++) {
                uint32_t afr[4][4];
                uint32_t bfr[4][2];
#pragma unroll
                for (int mi = 0; mi < 4; mi++) {
                    uint32_t c8 = (uint32_t)(((ks << 1) | a_hi) ^ xk);
                    uint32_t addr = a_base + (uint32_t)(a_row_l + mi * 16) * 128u + (c8 << 4);
                    ldsm_x4(afr[mi], addr);
                }
#pragma unroll
                for (int p = 0; p < 2; p++) {
                    uint32_t c8 = (uint32_t)(((ks << 1) | b_lo) ^ xk);
                    uint32_t addr = b_base + (uint32_t)(b_row_l + p * 16) * 128u + (c8 << 4);
                    uint32_t rr[4];
                    ldsm_x4(rr, addr);
                    bfr[2 * p][0] = rr[0]; bfr[2 * p][1] = rr[1];
                    bfr[2 * p + 1][0] = rr[2]; bfr[2 * p + 1][1] = rr[3];
                }
#pragma unroll
                for (int mi = 0; mi < 4; mi++)
#pragma unroll
                    for (int ni = 0; ni < 4; ni++)
                        mma_m16n8k16(acc[mi][ni], afr[mi], bfr[ni]);
            }
        }

        // grab next ticket early: atomic latency hides under drain + epilogue
        if (tid == 0) s_next = atomicAdd(&g_tile_ctr, 1);

        asm volatile("cp.async.wait_group 0;" ::: "memory");

        // epilogue: + bias (W_7 fold) + GELU + streaming stores
        const int grow0 = mt * TILE_M + warp_m * 64 + lane4;
        const int gcol0 = nt * TILE_N + warp_n * 32 + 2 * lanem;

        float bias2[4][2];
#pragma unroll
        for (int ni = 0; ni < 4; ni++) {
#pragma unroll
            for (int t = 0; t < 2; t++) {
                int cc = gcol0 + ni * 8 + t;
                float4 p = *reinterpret_cast<const float4*>(&g_biasp[cc][0]);
                bias2[ni][t] = (p.x + p.y) + (p.z + p.w);
            }
        }

#pragma unroll
        for (int mi = 0; mi < 4; mi++) {
#pragma unroll
            for (int ni = 0; ni < 4; ni++) {
                int rr = grow0 + mi * 16;
                int c = gcol0 + ni * 8;
                stg_cs_v2(out + (size_t)rr * DDIM + c,
                          gelu_exact(acc[mi][ni][0] + bias2[ni][0]),
                          gelu_exact(acc[mi][ni][1] + bias2[ni][1]));
                stg_cs_v2(out + (size_t)(rr + 8) * DDIM + c,
                          gelu_exact(acc[mi][ni][2] + bias2[ni][0]),
                          gelu_exact(acc[mi][ni][3] + bias2[ni][1]));
            }
        }

        __syncthreads();      // s_next visible to all; smem stages free for next tile
        tile = s_next;
    }
}

// ---------------- launch ----------------
extern "C" void kernel_launch(void* const* d_in, const int* in_sizes, int n_in,
                              void* d_out, int out_size) {
    const float* x  = (const float*)d_in[0];
    const float* bw = (const float*)d_in[1];
    const float* sw = (const float*)d_in[2];
    const float* ss = (const float*)d_in[3];
    float* out = (float*)d_out;

    cudaFuncSetAttribute(gemm_kernel, cudaFuncAttributeMaxDynamicSharedMemorySize, DYN_SMEM);

    prep_kernel<<<ACT_BLOCKS + W_BLOCKS, 256>>>(x, bw, sw, ss);
    gemm_kernel<<<GRID, GTHREADS, DYN_SMEM>>>(out);
}

// round 17
// speedup vs baseline: 1.0118x; 1.0118x over previous
#include <cuda_runtime.h>
#include <cuda_fp16.h>
#include <cstdint>
#include <cstddef>

// ---------------- problem dims (fixed) ----------------
#define NTOK 8192            // 4*2048 tokens
#define HDIM 1024
#define DDIM 4096
// K reduced 9216 -> 8192 via B-spline partition of unity (W_7 folds into a bias).
#define KDIM 8192

// ---------------- GEMM tiling (R15 champion config) ----------------
#define TILE_M 128
#define TILE_N 128
#define KCHUNK 64            // fp16 elems per k-iter = 128 bytes per row
#define STAGES 3
#define NIT (KDIM / KCHUNK)  // 128
#define GTHREADS 256         // 8 warps: 2 (M) x 4 (N), warp tile 64x32
#define MT (NTOK / TILE_M)   // 64
#define NT (DDIM / TILE_N)   // 32
#define NTILES (MT * NT)     // 2048
#define GRID 304             // 2 CTAs/SM * 152 SMs; persistent + work stealing

#define A_STAGE_BYTES (TILE_M * 128)   // 16384
#define B_STAGE_BYTES (TILE_N * 128)   // 16384
#define STAGE_BYTES (A_STAGE_BYTES + B_STAGE_BYTES)
#define DYN_SMEM (STAGES * STAGE_BYTES + 1024)   // ~97 KB -> 2 CTAs/SM

// ---------------- scratch (allocation-free: __device__ globals) ----------------
__device__ __half g_act[(size_t)NTOK * KDIM];   // 134 MB fp16 features
__device__ __half g_w[(size_t)DDIM * KDIM];     // 67 MB fp16 fused weights
__device__ float g_biasp[DDIM][4];              // 4 deterministic bias partials per output
__device__ int g_tile_ctr;                      // work-stealing ticket counter

// ---------------- helpers ----------------
__device__ __forceinline__ void cp_async16(uint32_t dst, const void* src) {
    asm volatile("cp.async.cg.shared.global [%0], [%1], 16;"
                 :: "r"(dst), "l"(src) : "memory");
}

__device__ __forceinline__ float gelu_exact(float v) {
    return 0.5f * v * (1.0f + erff(v * 0.70710678118654752f));
}

__device__ __forceinline__ void ldsm_x4(uint32_t* r, uint32_t addr) {
    asm volatile("ldmatrix.sync.aligned.m8n8.x4.shared.b16 {%0,%1,%2,%3}, [%4];"
                 : "=r"(r[0]), "=r"(r[1]), "=r"(r[2]), "=r"(r[3]) : "r"(addr));
}

__device__ __forceinline__ void mma_m16n8k16(float* c, const uint32_t* a, const uint32_t* b) {
    asm volatile(
        "mma.sync.aligned.m16n8k16.row.col.f32.f16.f16.f32 "
        "{%0,%1,%2,%3}, {%4,%5,%6,%7}, {%8,%9}, {%0,%1,%2,%3};"
        : "+f"(c[0]), "+f"(c[1]), "+f"(c[2]), "+f"(c[3])
        : "r"(a[0]), "r"(a[1]), "r"(a[2]), "r"(a[3]), "r"(b[0]), "r"(b[1]));
}

// streaming (evict-first) 8-byte store
__device__ __forceinline__ void stg_cs_v2(float* ptr, float x, float y) {
    asm volatile("st.global.cs.v2.f32 [%0], {%1, %2};"
                 :: "l"(ptr), "f"(x), "f"(y) : "memory");
}

// pack 8 floats -> uint4 of fp16
__device__ __forceinline__ uint4 pack8_h(const float* v) {
    union { __half2 h2[4]; uint4 u; } u;
    u.h2[0] = __floats2half2_rn(v[0], v[1]);
    u.h2[1] = __floats2half2_rn(v[2], v[3]);
    u.h2[2] = __floats2half2_rn(v[4], v[5]);
    u.h2[3] = __floats2half2_rn(v[6], v[7]);
    return u.u;
}

// closed-form uniform cubic B-spline features for one x: v[0]=silu, v[1..7]=B_0..B_6
__device__ __forceinline__ void features8(float xv, float* v) {
    float sig = 1.0f / (1.0f + __expf(-xv));
    float silu = xv * sig;

    float t25 = (xv + 1.0f) * 2.5f;
    int i = (int)t25;
    i = i < 0 ? 0 : (i > 4 ? 4 : i);
    float u = t25 - (float)i;
    float u2 = u * u;
    float u3 = u2 * u;
    float om = 1.0f - u;
    const float c6 = 1.0f / 6.0f;
    float b0 = om * om * om * c6;
    float b1 = (3.0f * u3 - 6.0f * u2 + 4.0f) * c6;
    float b2 = (-3.0f * u3 + 3.0f * u2 + 3.0f * u + 1.0f) * c6;
    float b3 = u3 * c6;

    v[0]=silu; v[1]=0.f; v[2]=0.f; v[3]=0.f; v[4]=0.f; v[5]=0.f; v[6]=0.f; v[7]=0.f;
    switch (i) {   // bases occupy slots 1+i .. 1+i+3 (B_7 folded into bias)
        case 0: v[1]=b0; v[2]=b1; v[3]=b2; v[4]=b3; break;
        case 1: v[2]=b0; v[3]=b1; v[4]=b2; v[5]=b3; break;
        case 2: v[3]=b0; v[4]=b1; v[5]=b2; v[6]=b3; break;
        case 3: v[4]=b0; v[5]=b1; v[6]=b2; v[7]=b3; break;
        default: v[5]=b0; v[6]=b1; v[7]=b2; break;
    }
}

// tile id -> (mt, nt), grouped 16x16 for L2 residency
__device__ __forceinline__ void map_tile(int t, int& mt, int& nt) {
    int g = t >> 8;
    int r = t & 255;
    mt = ((g & 3) << 4) | (r & 15);
    nt = ((g >> 2) << 4) | (r >> 4);
}

// ---------------- merged prep kernel ----------------
// act part: 2 elements per thread (float2 read, 2x ILP, 32B coalesced stores)
#define ACT_BLOCKS ((NTOK * HDIM) / (256 * 2))   // 16384
#define W_BLOCKS ((DDIM * HDIM) / 256)           // 16384

__global__ void __launch_bounds__(256) prep_kernel(const float* __restrict__ x,
                                                   const float* __restrict__ bw,
                                                   const float* __restrict__ sw,
                                                   const float* __restrict__ ss) {
    __shared__ float red[8];
    if (blockIdx.x == 0 && threadIdx.x == 0)
        g_tile_ctr = GRID;   // reset stealing counter every launch (prep precedes gemm)

    if (blockIdx.x < ACT_BLOCKS) {
        int idx2 = blockIdx.x * 256 + threadIdx.x;     // group of 2 elements
        float2 xv2 = reinterpret_cast<const float2*>(x)[idx2];

        int base_idx = idx2 << 1;                      // element index (h mult of 2)
        int n = base_idx >> 10;
        int h0 = base_idx & 1023;
        __half* dst = &g_act[(size_t)n * KDIM + 8 * (size_t)h0];

        float v0[8], v1[8];
        features8(xv2.x, v0);    // two independent chains: MUFU/FMA latencies overlap
        features8(xv2.y, v1);
        uint4 p0 = pack8_h(v0);
        uint4 p1 = pack8_h(v1);
        reinterpret_cast<uint4*>(dst)[0] = p0;
        reinterpret_cast<uint4*>(dst)[1] = p1;
    } else {
        int bidx = blockIdx.x - ACT_BLOCKS;
        int idx = bidx * 256 + threadIdx.x;
        float base = bw[idx];
        float scal = ss[idx];
        int d = idx >> 10;
        int h = idx & 1023;

        const float4* swp = reinterpret_cast<const float4*>(sw + (size_t)idx * 8);
        float4 s0 = swp[0], s1 = swp[1];
        float w7 = s1.w * scal;

        float w[8];
        w[0] = base;
        w[1] = s0.x * scal - w7; w[2] = s0.y * scal - w7;
        w[3] = s0.z * scal - w7; w[4] = s0.w * scal - w7;
        w[5] = s1.x * scal - w7; w[6] = s1.y * scal - w7;
        w[7] = s1.z * scal - w7;

        *reinterpret_cast<uint4*>(&g_w[(size_t)d * KDIM + 8 * (size_t)h]) = pack8_h(w);

        // deterministic bias partial: sum of w7 over this block's 256 h-values
        float s = w7;
#pragma unroll
        for (int m = 16; m > 0; m >>= 1)
            s += __shfl_xor_sync(0xFFFFFFFFu, s, m);
        if ((threadIdx.x & 31) == 0) red[threadIdx.x >> 5] = s;
        __syncthreads();
        if (threadIdx.x == 0) {
            float t = ((red[0] + red[1]) + (red[2] + red[3]))
                    + ((red[4] + red[5]) + (red[6] + red[7]));
            g_biasp[d][bidx & 3] = t;
        }
    }
}

// ---------------- GEMM: issue cp.async for k-iter `it` into stage `s` ----------------
__device__ __forceinline__ void issue_loads(uint32_t smem_base,
                                            const char* a_gbase, const char* b_gbase,
                                            int it, int s, int tid) {
    uint32_t a_s = smem_base + (uint32_t)s * STAGE_BYTES;
    uint32_t b_s = a_s + A_STAGE_BYTES;
    const char* a_g = a_gbase + (size_t)it * 128;   // 64 halfs = 128 B per k-iter
    const char* b_g = b_gbase + (size_t)it * 128;

#pragma unroll
    for (int i = 0; i < 4; i++) {
        int c = tid + i * GTHREADS;
        int row = c >> 3, c8 = c & 7;
        uint32_t off = ((uint32_t)row << 7) | ((uint32_t)c8 << 4);
        uint32_t swz = off ^ ((off >> 3) & 0x70u);
        cp_async16(a_s + swz, a_g + (size_t)row * (KDIM * 2) + ((size_t)c8 << 4));
    }
#pragma unroll
    for (int i = 0; i < 4; i++) {
        int c = tid + i * GTHREADS;
        int row = c >> 3, c8 = c & 7;
        uint32_t off = ((uint32_t)row << 7) | ((uint32_t)c8 << 4);
        uint32_t swz = off ^ ((off >> 3) & 0x70u);
        cp_async16(b_s + swz, b_g + (size_t)row * (KDIM * 2) + ((size_t)c8 << 4));
    }
}

// ---------------- persistent GEMM kernel (2 CTAs/SM, work-stealing tiles) ----------------
__global__ void __launch_bounds__(GTHREADS, 2) gemm_kernel(float* __restrict__ out) {
    extern __shared__ char dsmem[];
    __shared__ int s_next;

    const int tid = threadIdx.x;
    const int wid = tid >> 5;
    const int lane = tid & 31;
    const int lane4 = lane >> 2;
    const int lanem = lane & 3;
    const int warp_m = wid & 1;
    const int warp_n = wid >> 1;

    uint32_t smem_raw = (uint32_t)__cvta_generic_to_shared(dsmem);
    uint32_t smem_base = (smem_raw + 1023u) & ~1023u;

    const int xk = lane & 7;
    const int a_row_l = warp_m * 64 + (lane & 15);
    const int a_hi = lane >> 4;
    const int quad = lane >> 3;
    const int b_row_l = warp_n * 32 + ((quad >> 1) << 3) + (lane & 7);
    const int b_lo = quad & 1;

    int tile = blockIdx.x;
    while (tile < NTILES) {
        int mt, nt;
        map_tile(tile, mt, nt);

        const char* a_gbase = (const char*)(g_act + (size_t)mt * TILE_M * KDIM);
        const char* b_gbase = (const char*)(g_w + (size_t)nt * TILE_N * KDIM);

        float acc[4][4][4];
#pragma unroll
        for (int mi = 0; mi < 4; mi++)
#pragma unroll
            for (int ni = 0; ni < 4; ni++)
#pragma unroll
                for (int j = 0; j < 4; j++) acc[mi][ni][j] = 0.0f;

#pragma unroll
        for (int it = 0; it < STAGES - 1; it++) {
            issue_loads(smem_base, a_gbase, b_gbase, it, it, tid);
            asm volatile("cp.async.commit_group;" ::: "memory");
        }

        int cs = 0;
        int ls = STAGES - 1;
        for (int it = 0; it < NIT; it++) {
            asm volatile("cp.async.wait_group 1;" ::: "memory");
            __syncthreads();

            const int nx = it + STAGES - 1;
            if (nx < NIT) issue_loads(smem_base, a_gbase, b_gbase, nx, ls, tid);
            if (++ls == STAGES) ls = 0;
            asm volatile("cp.async.commit_group;" ::: "memory");

            const uint32_t a_base = smem_base + (uint32_t)cs * STAGE_BYTES;
            const uint32_t b_base = a_base + A_STAGE_BYTES;
            if (++cs == STAGES) cs = 0;

#pragma unroll
            for (int ks = 0; ks < 4; ks++) {
                uint32_t afr[4][4];
                uint32_t bfr[4][2];
#pragma unroll
                for (int mi = 0; mi < 4; mi++) {
                    uint32_t c8 = (uint32_t)(((ks << 1) | a_hi) ^ xk);
                    uint32_t addr = a_base + (uint32_t)(a_row_l + mi * 16) * 128u + (c8 << 4);
                    ldsm_x4(afr[mi], addr);
                }
#pragma unroll
                for (int p = 0; p < 2; p++) {
                    uint32_t c8 = (uint32_t)(((ks << 1) | b_lo) ^ xk);
                    uint32_t addr = b_base + (uint32_t)(b_row_l + p * 16) * 128u + (c8 << 4);
                    uint32_t rr[4];
                    ldsm_x4(rr, addr);
                    bfr[2 * p][0] = rr[0]; bfr[2 * p][1] = rr[1];
                    bfr[2 * p + 1][0] = rr[2]; bfr[2 * p + 1][1] = rr[3];
                }
#pragma unroll
                for (int mi = 0; mi < 4; mi++)
#pragma unroll
                    for (int ni = 0; ni < 4; ni++)
                        mma_m16n8k16(acc[mi][ni], afr[mi], bfr[ni]);
            }
        }

        // grab next ticket early: atomic latency hides under drain + epilogue
        if (tid == 0) s_next = atomicAdd(&g_tile_ctr, 1);

        asm volatile("cp.async.wait_group 0;" ::: "memory");

        // epilogue: + bias (W_7 fold) + GELU + streaming stores
        const int grow0 = mt * TILE_M + warp_m * 64 + lane4;
        const int gcol0 = nt * TILE_N + warp_n * 32 + 2 * lanem;

        float bias2[4][2];
#pragma unroll
        for (int ni = 0; ni < 4; ni++) {
#pragma unroll
            for (int t = 0; t < 2; t++) {
                int cc = gcol0 + ni * 8 + t;
                float4 p = *reinterpret_cast<const float4*>(&g_biasp[cc][0]);
                bias2[ni][t] = (p.x + p.y) + (p.z + p.w);
            }
        }

#pragma unroll
        for (int mi = 0; mi < 4; mi++) {
#pragma unroll
            for (int ni = 0; ni < 4; ni++) {
                int rr = grow0 + mi * 16;
                int c = gcol0 + ni * 8;
                stg_cs_v2(out + (size_t)rr * DDIM + c,
                          gelu_exact(acc[mi][ni][0] + bias2[ni][0]),
                          gelu_exact(acc[mi][ni][1] + bias2[ni][1]));
                stg_cs_v2(out + (size_t)(rr + 8) * DDIM + c,
                          gelu_exact(acc[mi][ni][2] + bias2[ni][0]),
                          gelu_exact(acc[mi][ni][3] + bias2[ni][1]));
            }
        }

        __syncthreads();      // s_next visible to all; smem stages free for next tile
        tile = s_next;
    }
}

// ---------------- launch ----------------
extern "C" void kernel_launch(void* const* d_in, const int* in_sizes, int n_in,
                              void* d_out, int out_size) {
    const float* x  = (const float*)d_in[0];
    const float* bw = (const float*)d_in[1];
    const float* sw = (const float*)d_in[2];
    const float* ss = (const float*)d_in[3];
    float* out = (float*)d_out;

    cudaFuncSetAttribute(gemm_kernel, cudaFuncAttributeMaxDynamicSharedMemorySize, DYN_SMEM);

    prep_kernel<<<ACT_BLOCKS + W_BLOCKS, 256>>>(x, bw, sw, ss);
    gemm_kernel<<<GRID, GTHREADS, DYN_SMEM>>>(out);
}